// round 1
// baseline (speedup 1.0000x reference)
#include <cuda_runtime.h>
#include <cuda_bf16.h>

// Problem constants (fixed shapes for this registered problem)
#define B_  2
#define C_  32
#define T_  8
#define H_  32
#define W_  32
#define V_  8192
#define N_  16384          // B*T*H*W query rows
#define NELEM_ 524288      // B*C*T*H*W
#define THW_ 8192          // T*H*W

// ---------------- device scratch (no allocations allowed) ----------------
__device__ float g_ee[V_];        // ||e||^2 per code
__device__ int   g_idx[N_];       // argmin index per query row
__device__ int   g_counts[V_];    // bincount
__device__ float g_g[NELEM_];     // gathered emb field (conv input)
__device__ float g_loss;          // sum of squared diff
__device__ int   g_used;          // # codes used

// ---------------- init: zero accumulators ----------------
__global__ void init_kernel() {
    int i = blockIdx.x * blockDim.x + threadIdx.x;
    if (i < V_) g_counts[i] = 0;
    if (i == 0) { g_loss = 0.f; g_used = 0; }
}

// ---------------- ee: per-code squared norm ----------------
__global__ void ee_kernel(const float* __restrict__ emb) {
    int v = blockIdx.x * blockDim.x + threadIdx.x;
    if (v >= V_) return;
    const float4* e4 = reinterpret_cast<const float4*>(emb) + v * 8;
    float s = 0.f;
#pragma unroll
    for (int i = 0; i < 8; i++) {
        float4 e = e4[i];
        s = fmaf(e.x, e.x, s);
        s = fmaf(e.y, e.y, s);
        s = fmaf(e.z, e.z, s);
        s = fmaf(e.w, e.w, s);
    }
    g_ee[v] = s;
}

// ---------------- argmin over V codes ----------------
// 64 rows per block, 4 threads per row (code partitions), 256 threads.
// Codes staged in shared 128 at a time; all lanes of a warp share p -> broadcast LDS.
__global__ __launch_bounds__(256) void argmin_kernel(
    const float* __restrict__ f, const float* __restrict__ emb)
{
    __shared__ float e_s[128 * 32];
    __shared__ float ee_s[128];
    __shared__ float rv[256];
    __shared__ int   ri[256];

    const int tid = threadIdx.x;
    const int p = tid >> 6;        // code partition 0..3
    const int r = tid & 63;        // local row
    const int row = blockIdx.x * 64 + r;
    const int b = row >> 13;       // row / 8192
    const int thw = row & 8191;

    // load q (32 strided floats) into registers, compute ||q||^2
    const float* fq = f + b * (C_ * THW_) + thw;
    float4 q4[8];
    float qq = 0.f;
#pragma unroll
    for (int v = 0; v < 8; v++) {
        float a = fq[(4 * v + 0) * THW_];
        float bb = fq[(4 * v + 1) * THW_];
        float c = fq[(4 * v + 2) * THW_];
        float d = fq[(4 * v + 3) * THW_];
        q4[v] = make_float4(a, bb, c, d);
        qq = fmaf(a, a, qq); qq = fmaf(bb, bb, qq);
        qq = fmaf(c, c, qq); qq = fmaf(d, d, qq);
    }

    float minv = 3.402823466e+38f;
    int   mini = 0x7fffffff;

    const float4* embg = reinterpret_cast<const float4*>(emb);
    float4* es4 = reinterpret_cast<float4*>(e_s);

    for (int cb = 0; cb < V_; cb += 128) {
        // cooperative stage of 128 codes (4096 floats) + their norms
#pragma unroll
        for (int i = 0; i < 4; i++)
            es4[tid + 256 * i] = embg[cb * 8 + tid + 256 * i];
        if (tid < 128) ee_s[tid] = g_ee[cb + tid];
        __syncthreads();

#pragma unroll 2
        for (int j = 0; j < 32; j++) {
            const int c = p + (j << 2);
            const float4* e4 = reinterpret_cast<const float4*>(e_s + (c << 5));
            float a0 = 0.f, a1 = 0.f, a2 = 0.f, a3 = 0.f;
#pragma unroll
            for (int v = 0; v < 8; v++) {
                float4 ev = e4[v];
                float4 qv = q4[v];
                a0 = fmaf(qv.x, ev.x, a0);
                a1 = fmaf(qv.y, ev.y, a1);
                a2 = fmaf(qv.z, ev.z, a2);
                a3 = fmaf(qv.w, ev.w, a3);
            }
            float dot = (a0 + a1) + (a2 + a3);
            float dist = fmaf(-2.f, dot, qq + ee_s[c]);
            if (dist < minv) { minv = dist; mini = cb + c; }
        }
        __syncthreads();
    }

    rv[tid] = minv;
    ri[tid] = mini;
    __syncthreads();
    if (p == 0) {
        float bv = rv[tid];
        int   bi = ri[tid];
#pragma unroll
        for (int k = 1; k < 4; k++) {
            float v2 = rv[tid + 64 * k];
            int   i2 = ri[tid + 64 * k];
            if (v2 < bv || (v2 == bv && i2 < bi)) { bv = v2; bi = i2; }
        }
        g_idx[row] = bi;
        atomicAdd(&g_counts[bi], 1);
    }
}

// ---------------- gather emb rows into NCDHW field ----------------
__global__ void gather_kernel(const float* __restrict__ emb) {
    int i = blockIdx.x * blockDim.x + threadIdx.x;
    if (i >= NELEM_) return;
    int b = i / (C_ * THW_);
    int c = (i / THW_) & (C_ - 1);
    int thw = i & (THW_ - 1);
    int rowq = b * THW_ + thw;
    g_g[i] = emb[g_idx[rowq] * C_ + c];
}

// ---------------- conv3d 3x3x3 SAME + blend + mse partial ----------------
// Block: one (b, t, h-tile of 4). 128 threads = (w=32, hl=4). Each thread
// computes all 32 output channels at its (h,w). ci staged in chunks of 8.
__global__ __launch_bounds__(128) void conv_kernel(
    const float* __restrict__ f, const float* __restrict__ cw,
    const float* __restrict__ cbias, float* __restrict__ out)
{
    __shared__ float ps[8 * 3 * 6 * 34];   // [cil][tt][hh][ww]
    __shared__ float ws[8 * 27 * 32];      // [cil][kk][co]
    __shared__ float bias_s[32];
    __shared__ float red[4];

    const int tid = threadIdx.x;
    const int bi = blockIdx.x;
    const int ht = bi & 7;
    const int t  = (bi >> 3) & 7;
    const int b  = bi >> 6;
    const int h0 = ht * 4;
    const int w  = tid & 31;
    const int hl = tid >> 5;

    if (tid < 32) bias_s[tid] = cbias[tid];

    float acc[32];
#pragma unroll
    for (int i = 0; i < 32; i++) acc[i] = 0.f;

#pragma unroll 1
    for (int ci0 = 0; ci0 < 32; ci0 += 8) {
        __syncthreads();
        // stage input patch (zero-padded)
        for (int i = tid; i < 8 * 3 * 6 * 34; i += 128) {
            int ww = i % 34;
            int r2 = i / 34;
            int hh = r2 % 6; r2 /= 6;
            int tt = r2 % 3;
            int cil = r2 / 3;
            int gt = t + tt - 1, gh = h0 + hh - 1, gw = ww - 1;
            float v = 0.f;
            if (gt >= 0 && gt < T_ && gh >= 0 && gh < H_ && gw >= 0 && gw < W_)
                v = g_g[b * (C_ * THW_) + (ci0 + cil) * THW_ + gt * 1024 + gh * 32 + gw];
            ps[i] = v;
        }
        // stage weights re-laid-out co-contiguous
        for (int i = tid; i < 8 * 27 * 32; i += 128) {
            int co = i & 31;
            int r2 = i >> 5;
            int kk = r2 % 27;
            int cil = r2 / 27;
            ws[i] = cw[(co * 32 + ci0 + cil) * 27 + kk];
        }
        __syncthreads();

#pragma unroll 1
        for (int cil = 0; cil < 8; cil++) {
#pragma unroll 1
            for (int kt = 0; kt < 3; kt++) {
#pragma unroll
                for (int kh = 0; kh < 3; kh++) {
#pragma unroll
                    for (int kw = 0; kw < 3; kw++) {
                        float pv = ps[((cil * 3 + kt) * 6 + hl + kh) * 34 + w + kw];
                        const float4* wv = reinterpret_cast<const float4*>(
                            &ws[(cil * 27 + (kt * 9 + kh * 3 + kw)) * 32]);
#pragma unroll
                        for (int g4 = 0; g4 < 8; g4++) {
                            float4 wq = wv[g4];
                            acc[g4 * 4 + 0] = fmaf(pv, wq.x, acc[g4 * 4 + 0]);
                            acc[g4 * 4 + 1] = fmaf(pv, wq.y, acc[g4 * 4 + 1]);
                            acc[g4 * 4 + 2] = fmaf(pv, wq.z, acc[g4 * 4 + 2]);
                            acc[g4 * 4 + 3] = fmaf(pv, wq.w, acc[g4 * 4 + 3]);
                        }
                    }
                }
            }
        }
    }

    // epilogue: blend, store, squared-diff
    const int h = h0 + hl;
    float sq = 0.f;
    const int base = b * (C_ * THW_) + t * 1024 + h * 32 + w;
#pragma unroll
    for (int co = 0; co < 32; co++) {
        int o = base + co * THW_;
        float gv = g_g[o];
        float val = 0.5f * gv + 0.5f * (acc[co] + bias_s[co]);
        out[o] = val;
        float d = val - f[o];
        sq = fmaf(d, d, sq);
    }
#pragma unroll
    for (int off = 16; off > 0; off >>= 1)
        sq += __shfl_down_sync(0xffffffffu, sq, off);
    if ((tid & 31) == 0) red[tid >> 5] = sq;
    __syncthreads();
    if (tid == 0) atomicAdd(&g_loss, (red[0] + red[1]) + (red[2] + red[3]));
}

// ---------------- usage count ----------------
__global__ void usage_kernel() {
    int v = blockIdx.x * blockDim.x + threadIdx.x;
    bool u = (v < V_) && (g_counts[v] > 0);
    unsigned m = __ballot_sync(0xffffffffu, u);
    if ((threadIdx.x & 31) == 0) atomicAdd(&g_used, __popc(m));
}

// ---------------- finalize scalars ----------------
__global__ void finalize_kernel(float* __restrict__ out, int write_scalars) {
    if (!write_scalars) return;
    out[NELEM_]     = 1.25f * g_loss * (1.0f / (float)NELEM_);
    out[NELEM_ + 1] = 100.0f * (float)g_used / (float)V_;
}

extern "C" void kernel_launch(void* const* d_in, const int* in_sizes, int n_in,
                              void* d_out, int out_size) {
    const float* f    = (const float*)d_in[0];
    const float* emb  = (const float*)d_in[1];
    const float* cw   = (const float*)d_in[2];
    const float* cb   = (const float*)d_in[3];
    float* out = (float*)d_out;
    int write_scalars = (out_size >= NELEM_ + 2) ? 1 : 0;

    init_kernel<<<V_ / 256, 256>>>();
    ee_kernel<<<V_ / 256, 256>>>(emb);
    argmin_kernel<<<N_ / 64, 256>>>(f, emb);
    gather_kernel<<<NELEM_ / 256, 256>>>(emb);
    conv_kernel<<<B_ * T_ * (H_ / 4), 128>>>(f, cw, cb, out);
    usage_kernel<<<V_ / 256, 256>>>();
    finalize_kernel<<<1, 1>>>(out, write_scalars);
}

// round 3
// speedup vs baseline: 1.0379x; 1.0379x over previous
#include <cuda_runtime.h>
#include <cuda_bf16.h>
#include <cstdint>

// Problem constants (fixed shapes)
#define B_  2
#define C_  32
#define T_  8
#define H_  32
#define W_  32
#define V_  8192
#define N_  16384          // B*T*H*W query rows
#define NELEM_ 524288      // B*C*T*H*W
#define THW_ 8192          // T*H*W
#define NPAIR_ 4096        // V/2
#define PKW_ 17            // float4 per packed code-pair (34 float2 entries)

typedef unsigned long long u64;
typedef unsigned int u32;

// ---------------- device scratch ----------------
__device__ float4 g_pk[NPAIR_ * PKW_];   // packed codebook pairs
__device__ int   g_idx[N_];
__device__ int   g_counts[V_];
__device__ float g_g[NELEM_];
__device__ float g_loss;
__device__ int   g_used;

// ---------------- packed fp32x2 helpers ----------------
__device__ __forceinline__ u64 ffma2(u64 a, u64 b, u64 c) {
    u64 d;
    asm("fma.rn.f32x2 %0, %1, %2, %3;" : "=l"(d) : "l"(a), "l"(b), "l"(c));
    return d;
}
__device__ __forceinline__ u64 fadd2(u64 a, u64 b) {
    u64 d;
    asm("add.rn.f32x2 %0, %1, %2;" : "=l"(d) : "l"(a), "l"(b));
    return d;
}
__device__ __forceinline__ u64 pack2(float lo, float hi) {
    u64 d; asm("mov.b64 %0, {%1, %2};" : "=l"(d) : "f"(lo), "f"(hi)); return d;
}
__device__ __forceinline__ void unpack2(u64 v, float& lo, float& hi) {
    asm("mov.b64 {%0, %1}, %2;" : "=f"(lo), "=f"(hi) : "l"(v));
}

// ---------------- pack codebook + zero accumulators ----------------
// One thread per code pair: writes [pair][ch] = (eA[ch], eB[ch]) for ch=0..31,
// entry 32 = (-0.5*||eA||^2, -0.5*||eB||^2) (q-multiplier 1), entry 33 = (0,0).
__global__ void pack_kernel(const float* __restrict__ emb) {
    int pp = blockIdx.x * blockDim.x + threadIdx.x;
    if (pp >= NPAIR_) return;
    g_counts[2 * pp] = 0;
    g_counts[2 * pp + 1] = 0;
    if (pp == 0) { g_loss = 0.f; g_used = 0; }

    const float4* ea = reinterpret_cast<const float4*>(emb) + (2 * pp) * 8;
    const float4* eb = ea + 8;
    float2* dst = reinterpret_cast<float2*>(g_pk + pp * PKW_);
    float eeA = 0.f, eeB = 0.f;
#pragma unroll
    for (int i = 0; i < 8; i++) {
        float4 a = ea[i], b = eb[i];
        eeA = fmaf(a.x, a.x, eeA); eeA = fmaf(a.y, a.y, eeA);
        eeA = fmaf(a.z, a.z, eeA); eeA = fmaf(a.w, a.w, eeA);
        eeB = fmaf(b.x, b.x, eeB); eeB = fmaf(b.y, b.y, eeB);
        eeB = fmaf(b.z, b.z, eeB); eeB = fmaf(b.w, b.w, eeB);
        dst[4 * i + 0] = make_float2(a.x, b.x);
        dst[4 * i + 1] = make_float2(a.y, b.y);
        dst[4 * i + 2] = make_float2(a.z, b.z);
        dst[4 * i + 3] = make_float2(a.w, b.w);
    }
    dst[32] = make_float2(-0.5f * eeA, -0.5f * eeB);
    dst[33] = make_float2(0.f, 0.f);
}

// ---------------- argmin (as argmax of q.e - 0.5||e||^2) ----------------
// 32 rows/block, 4 code partitions, 128 threads, 512 blocks.
// Chunk of 128 codes (64 pairs) staged in shared; inner loop is pure FFMA2.
__global__ __launch_bounds__(128) void argmin_kernel(const float* __restrict__ f) {
    __shared__ __align__(16) float4 es[64 * PKW_];   // 1088 float4
    __shared__ float rv[128];
    __shared__ int   ri[128];

    const int tid = threadIdx.x;
    const int r = tid & 31;        // row within block
    const int p = tid >> 5;        // code partition 0..3
    const int row = blockIdx.x * 32 + r;
    const int b = row >> 13;
    const int thw = row & 8191;

    // load q (channel-strided) and build duplicated-lane packed q
    const float* fq = f + b * (C_ * THW_) + thw;
    u64 qp[34];
#pragma unroll
    for (int ch = 0; ch < 32; ch++) {
        float qv = fq[ch * THW_];
        qp[ch] = pack2(qv, qv);
    }
    qp[32] = pack2(1.f, 1.f);
    qp[33] = 0ull;

    u32 sbase;
    asm("{ .reg .u64 t; cvta.to.shared.u64 t, %1; cvt.u32.u64 %0, t; }"
        : "=r"(sbase) : "l"(es));

    float best = -3.402823466e+38f;
    int bi = 0;

    for (int cb = 0; cb < V_; cb += 128) {
        __syncthreads();
        const float4* src = g_pk + (cb >> 1) * PKW_;
#pragma unroll
        for (int i = 0; i < 9; i++) {
            int k = tid + 128 * i;
            if (k < 64 * PKW_) es[k] = src[k];
        }
        __syncthreads();

#pragma unroll 1
        for (int j = 0; j < 16; j++) {
            const int pl = p + (j << 2);               // pair within chunk
            u32 addr = sbase + pl * (PKW_ * 16);
            u64 a0 = 0, a1 = 0, a2 = 0, a3 = 0;
#pragma unroll
            for (int k = 0; k < 17; k++) {
                u64 e0, e1;
                asm("ld.shared.v2.b64 {%0, %1}, [%2];"
                    : "=l"(e0), "=l"(e1) : "r"(addr + k * 16));
                if ((k & 1) == 0) {
                    a0 = ffma2(e0, qp[2 * k], a0);
                    a1 = ffma2(e1, qp[2 * k + 1], a1);
                } else {
                    a2 = ffma2(e0, qp[2 * k], a2);
                    a3 = ffma2(e1, qp[2 * k + 1], a3);
                }
            }
            u64 s = fadd2(fadd2(a0, a2), fadd2(a1, a3));
            float sa, sb;
            unpack2(s, sa, sb);
            const int cA = cb + 2 * pl;
            if (sa > best) { best = sa; bi = cA; }
            if (sb > best) { best = sb; bi = cA + 1; }
        }
    }

    rv[tid] = best;
    ri[tid] = bi;
    __syncthreads();
    if (p == 0) {
        float bv = rv[tid];
        int bbi = ri[tid];
#pragma unroll
        for (int k = 1; k < 4; k++) {
            float v2 = rv[tid + 32 * k];
            int i2 = ri[tid + 32 * k];
            if (v2 > bv || (v2 == bv && i2 < bbi)) { bv = v2; bbi = i2; }
        }
        g_idx[row] = bbi;
        atomicAdd(&g_counts[bbi], 1);
    }
}

// ---------------- gather emb rows into NCDHW field ----------------
__global__ void gather_kernel(const float* __restrict__ emb) {
    int i = blockIdx.x * blockDim.x + threadIdx.x;
    if (i >= NELEM_) return;
    int b = i / (C_ * THW_);
    int c = (i / THW_) & (C_ - 1);
    int thw = i & (THW_ - 1);
    int rowq = b * THW_ + thw;
    g_g[i] = emb[g_idx[rowq] * C_ + c];
}

// ---------------- conv3d 3x3x3 SAME + blend + mse partial ----------------
__global__ __launch_bounds__(128) void conv_kernel(
    const float* __restrict__ f, const float* __restrict__ cw,
    const float* __restrict__ cbias, float* __restrict__ out)
{
    __shared__ float ps[8 * 3 * 6 * 34];   // [cil][tt][hh][ww]
    __shared__ float ws[8 * 27 * 32];      // [cil][kk][co]
    __shared__ float bias_s[32];
    __shared__ float red[4];

    const int tid = threadIdx.x;
    const int bi = blockIdx.x;
    const int ht = bi & 7;
    const int t  = (bi >> 3) & 7;
    const int b  = bi >> 6;
    const int h0 = ht * 4;
    const int w  = tid & 31;
    const int hl = tid >> 5;

    if (tid < 32) bias_s[tid] = cbias[tid];

    float acc[32];
#pragma unroll
    for (int i = 0; i < 32; i++) acc[i] = 0.f;

#pragma unroll 1
    for (int ci0 = 0; ci0 < 32; ci0 += 8) {
        __syncthreads();
        for (int i = tid; i < 8 * 3 * 6 * 34; i += 128) {
            int ww = i % 34;
            int r2 = i / 34;
            int hh = r2 % 6; r2 /= 6;
            int tt = r2 % 3;
            int cil = r2 / 3;
            int gt = t + tt - 1, gh = h0 + hh - 1, gw = ww - 1;
            float v = 0.f;
            if (gt >= 0 && gt < T_ && gh >= 0 && gh < H_ && gw >= 0 && gw < W_)
                v = g_g[b * (C_ * THW_) + (ci0 + cil) * THW_ + gt * 1024 + gh * 32 + gw];
            ps[i] = v;
        }
        for (int i = tid; i < 8 * 27 * 32; i += 128) {
            int co = i & 31;
            int r2 = i >> 5;
            int kk = r2 % 27;
            int cil = r2 / 27;
            ws[i] = cw[(co * 32 + ci0 + cil) * 27 + kk];
        }
        __syncthreads();

#pragma unroll 1
        for (int cil = 0; cil < 8; cil++) {
#pragma unroll 1
            for (int kt = 0; kt < 3; kt++) {
#pragma unroll
                for (int kh = 0; kh < 3; kh++) {
#pragma unroll
                    for (int kw = 0; kw < 3; kw++) {
                        float pv = ps[((cil * 3 + kt) * 6 + hl + kh) * 34 + w + kw];
                        const float4* wv = reinterpret_cast<const float4*>(
                            &ws[(cil * 27 + (kt * 9 + kh * 3 + kw)) * 32]);
#pragma unroll
                        for (int g4 = 0; g4 < 8; g4++) {
                            float4 wq = wv[g4];
                            acc[g4 * 4 + 0] = fmaf(pv, wq.x, acc[g4 * 4 + 0]);
                            acc[g4 * 4 + 1] = fmaf(pv, wq.y, acc[g4 * 4 + 1]);
                            acc[g4 * 4 + 2] = fmaf(pv, wq.z, acc[g4 * 4 + 2]);
                            acc[g4 * 4 + 3] = fmaf(pv, wq.w, acc[g4 * 4 + 3]);
                        }
                    }
                }
            }
        }
    }

    const int h = h0 + hl;
    float sq = 0.f;
    const int base = b * (C_ * THW_) + t * 1024 + h * 32 + w;
#pragma unroll
    for (int co = 0; co < 32; co++) {
        int o = base + co * THW_;
        float gv = g_g[o];
        float val = 0.5f * gv + 0.5f * (acc[co] + bias_s[co]);
        out[o] = val;
        float d = val - f[o];
        sq = fmaf(d, d, sq);
    }
#pragma unroll
    for (int off = 16; off > 0; off >>= 1)
        sq += __shfl_down_sync(0xffffffffu, sq, off);
    if ((tid & 31) == 0) red[tid >> 5] = sq;
    __syncthreads();
    if (tid == 0) atomicAdd(&g_loss, (red[0] + red[1]) + (red[2] + red[3]));
}

// ---------------- usage count ----------------
__global__ void usage_kernel() {
    int v = blockIdx.x * blockDim.x + threadIdx.x;
    bool u = (v < V_) && (g_counts[v] > 0);
    unsigned m = __ballot_sync(0xffffffffu, u);
    if ((threadIdx.x & 31) == 0) atomicAdd(&g_used, __popc(m));
}

// ---------------- finalize scalars ----------------
__global__ void finalize_kernel(float* __restrict__ out, int write_scalars) {
    if (!write_scalars) return;
    out[NELEM_]     = 1.25f * g_loss * (1.0f / (float)NELEM_);
    out[NELEM_ + 1] = 100.0f * (float)g_used / (float)V_;
}

extern "C" void kernel_launch(void* const* d_in, const int* in_sizes, int n_in,
                              void* d_out, int out_size) {
    const float* f    = (const float*)d_in[0];
    const float* emb  = (const float*)d_in[1];
    const float* cw   = (const float*)d_in[2];
    const float* cb   = (const float*)d_in[3];
    float* out = (float*)d_out;
    int write_scalars = (out_size >= NELEM_ + 2) ? 1 : 0;

    pack_kernel<<<NPAIR_ / 256, 256>>>(emb);
    argmin_kernel<<<N_ / 32, 128>>>(f);
    gather_kernel<<<NELEM_ / 256, 256>>>(emb);
    conv_kernel<<<B_ * T_ * (H_ / 4), 128>>>(f, cw, cb, out);
    usage_kernel<<<V_ / 256, 256>>>();
    finalize_kernel<<<1, 1>>>(out, write_scalars);
}

// round 4
// speedup vs baseline: 1.1857x; 1.1424x over previous
#include <cuda_runtime.h>
#include <cuda_bf16.h>
#include <cstdint>

// Problem constants (fixed shapes)
#define B_  2
#define C_  32
#define T_  8
#define H_  32
#define W_  32
#define V_  8192
#define N_  16384          // B*T*H*W query rows
#define NELEM_ 524288      // B*C*T*H*W
#define THW_ 8192          // T*H*W
#define NPAIR_ 4096        // V/2
#define PKW_ 17            // float4 per packed code-pair (34 float2 entries)
#define CHUNK_PAIRS_ 64
#define CHUNK_F4_ (CHUNK_PAIRS_ * PKW_)      // 1088 float4
#define CHUNK_BYTES_ (CHUNK_F4_ * 16)        // 17408 bytes
#define NCHUNK_ (NPAIR_ / CHUNK_PAIRS_)      // 64

typedef unsigned long long u64;
typedef unsigned int u32;

// ---------------- device scratch ----------------
__device__ float4 g_pk[NPAIR_ * PKW_];   // packed codebook pairs
__device__ int   g_idx[N_];
__device__ int   g_counts[V_];
__device__ float g_g[NELEM_];
__device__ float g_loss;
__device__ int   g_used;

// ---------------- packed fp32x2 helpers ----------------
__device__ __forceinline__ u64 ffma2(u64 a, u64 b, u64 c) {
    u64 d;
    asm("fma.rn.f32x2 %0, %1, %2, %3;" : "=l"(d) : "l"(a), "l"(b), "l"(c));
    return d;
}
__device__ __forceinline__ u64 fadd2(u64 a, u64 b) {
    u64 d;
    asm("add.rn.f32x2 %0, %1, %2;" : "=l"(d) : "l"(a), "l"(b));
    return d;
}
__device__ __forceinline__ u64 pack2(float lo, float hi) {
    u64 d; asm("mov.b64 %0, {%1, %2};" : "=l"(d) : "f"(lo), "f"(hi)); return d;
}
__device__ __forceinline__ void unpack2(u64 v, float& lo, float& hi) {
    asm("mov.b64 {%0, %1}, %2;" : "=f"(lo), "=f"(hi) : "l"(v));
}
__device__ __forceinline__ void cpasync16(u32 smem, const void* gmem) {
    asm volatile("cp.async.cg.shared.global [%0], [%1], 16;" :: "r"(smem), "l"(gmem));
}
__device__ __forceinline__ void cpcommit() {
    asm volatile("cp.async.commit_group;");
}
template <int K>
__device__ __forceinline__ void cpwait() {
    asm volatile("cp.async.wait_group %0;" :: "n"(K));
}

// ---------------- pack codebook + zero accumulators ----------------
__global__ void pack_kernel(const float* __restrict__ emb) {
    int pp = blockIdx.x * blockDim.x + threadIdx.x;
    if (pp >= NPAIR_) return;
    g_counts[2 * pp] = 0;
    g_counts[2 * pp + 1] = 0;
    if (pp == 0) { g_loss = 0.f; g_used = 0; }

    const float4* ea = reinterpret_cast<const float4*>(emb) + (2 * pp) * 8;
    const float4* eb = ea + 8;
    float2* dst = reinterpret_cast<float2*>(g_pk + pp * PKW_);
    float eeA = 0.f, eeB = 0.f;
#pragma unroll
    for (int i = 0; i < 8; i++) {
        float4 a = ea[i], b = eb[i];
        eeA = fmaf(a.x, a.x, eeA); eeA = fmaf(a.y, a.y, eeA);
        eeA = fmaf(a.z, a.z, eeA); eeA = fmaf(a.w, a.w, eeA);
        eeB = fmaf(b.x, b.x, eeB); eeB = fmaf(b.y, b.y, eeB);
        eeB = fmaf(b.z, b.z, eeB); eeB = fmaf(b.w, b.w, eeB);
        dst[4 * i + 0] = make_float2(a.x, b.x);
        dst[4 * i + 1] = make_float2(a.y, b.y);
        dst[4 * i + 2] = make_float2(a.z, b.z);
        dst[4 * i + 3] = make_float2(a.w, b.w);
    }
    dst[32] = make_float2(-0.5f * eeA, -0.5f * eeB);
    dst[33] = make_float2(0.f, 0.f);
}

// ---------------- argmin (argmax of q.e - 0.5||e||^2) ----------------
// 64 rows/block, 4 code partitions, 256 threads, 256 blocks.
// Double-buffered cp.async staging: copy chunk c+1 overlaps compute chunk c.
__global__ __launch_bounds__(256) void argmin_kernel(const float* __restrict__ f) {
    __shared__ __align__(16) float4 es[2][CHUNK_F4_];
    __shared__ float rv[256];
    __shared__ int   ri[256];

    const int tid = threadIdx.x;
    const int r = tid & 63;        // row within block
    const int p = tid >> 6;        // code partition 0..3
    const int row = blockIdx.x * 64 + r;
    const int b = row >> 13;
    const int thw = row & 8191;

    // load q (channel-strided), duplicated-lane packed
    const float* fq = f + b * (C_ * THW_) + thw;
    u64 qp[34];
#pragma unroll
    for (int ch = 0; ch < 32; ch++) {
        float qv = fq[ch * THW_];
        qp[ch] = pack2(qv, qv);
    }
    qp[32] = pack2(1.f, 1.f);
    qp[33] = 0ull;

    u32 sbase;
    asm("{ .reg .u64 t; cvta.to.shared.u64 t, %1; cvt.u32.u64 %0, t; }"
        : "=r"(sbase) : "l"(&es[0][0]));

    // prefetch chunk 0 into buffer 0
    {
        const float4* src = g_pk;
#pragma unroll
        for (int i = 0; i < 5; i++) {
            int k = tid + 256 * i;
            if (k < CHUNK_F4_) cpasync16(sbase + k * 16, src + k);
        }
        cpcommit();
    }

    float best = -3.402823466e+38f;
    int bi = 0;

#pragma unroll 1
    for (int c = 0; c < NCHUNK_; c++) {
        cpwait<0>();
        __syncthreads();   // chunk c visible to all; all done with buf[(c+1)&1] from c-1

        if (c + 1 < NCHUNK_) {
            const float4* src = g_pk + (c + 1) * CHUNK_F4_;
            u32 dst = sbase + ((c + 1) & 1) * CHUNK_BYTES_;
#pragma unroll
            for (int i = 0; i < 5; i++) {
                int k = tid + 256 * i;
                if (k < CHUNK_F4_) cpasync16(dst + k * 16, src + k);
            }
            cpcommit();
        }

        const u32 bufb = sbase + (c & 1) * CHUNK_BYTES_;
#pragma unroll 1
        for (int j = 0; j < 16; j++) {
            const int pl = p + (j << 2);               // pair within chunk
            u32 addr = bufb + pl * (PKW_ * 16);
            u64 a0 = 0, a1 = 0, a2 = 0, a3 = 0;
#pragma unroll
            for (int k = 0; k < 17; k++) {
                u64 e0, e1;
                asm("ld.shared.v2.b64 {%0, %1}, [%2];"
                    : "=l"(e0), "=l"(e1) : "r"(addr + k * 16));
                if ((k & 1) == 0) {
                    a0 = ffma2(e0, qp[2 * k], a0);
                    a1 = ffma2(e1, qp[2 * k + 1], a1);
                } else {
                    a2 = ffma2(e0, qp[2 * k], a2);
                    a3 = ffma2(e1, qp[2 * k + 1], a3);
                }
            }
            u64 s = fadd2(fadd2(a0, a2), fadd2(a1, a3));
            float sa, sb;
            unpack2(s, sa, sb);
            const int cA = (c * CHUNK_PAIRS_ + pl) * 2;
            if (sa > best) { best = sa; bi = cA; }
            if (sb > best) { best = sb; bi = cA + 1; }
        }
    }

    rv[tid] = best;
    ri[tid] = bi;
    __syncthreads();
    if (p == 0) {
        float bv = rv[tid];
        int bbi = ri[tid];
#pragma unroll
        for (int k = 1; k < 4; k++) {
            float v2 = rv[tid + 64 * k];
            int i2 = ri[tid + 64 * k];
            if (v2 > bv || (v2 == bv && i2 < bbi)) { bv = v2; bbi = i2; }
        }
        g_idx[row] = bbi;
        atomicAdd(&g_counts[bbi], 1);
    }
}

// ---------------- gather emb rows into NCDHW field ----------------
__global__ void gather_kernel(const float* __restrict__ emb) {
    int i = blockIdx.x * blockDim.x + threadIdx.x;
    if (i >= NELEM_) return;
    int b = i / (C_ * THW_);
    int c = (i / THW_) & (C_ - 1);
    int thw = i & (THW_ - 1);
    int rowq = b * THW_ + thw;
    g_g[i] = emb[g_idx[rowq] * C_ + c];
}

// ---------------- conv3d 3x3x3 SAME + blend + mse partial ----------------
// Block: (b, t, h-tile of 4). 512 threads = (w=32, hl=4, cog=4).
// Each thread computes 8 output channels at its (h,w).
__global__ __launch_bounds__(512) void conv_kernel(
    const float* __restrict__ f, const float* __restrict__ cw,
    const float* __restrict__ cbias, float* __restrict__ out)
{
    __shared__ float ps[8 * 3 * 6 * 34];   // [cil][tt][hh][ww]  4896
    __shared__ float ws[8 * 27 * 32];      // [cil][kk][co]      6912
    __shared__ float bias_s[32];
    __shared__ float red[16];

    const int tid = threadIdx.x;
    const int bi = blockIdx.x;
    const int ht = bi & 7;
    const int t  = (bi >> 3) & 7;
    const int b  = bi >> 6;
    const int h0 = ht * 4;
    const int w   = tid & 31;
    const int hl  = (tid >> 5) & 3;
    const int cog = tid >> 7;              // 0..3, co base = cog*8

    if (tid < 32) bias_s[tid] = cbias[tid];

    float acc[8];
#pragma unroll
    for (int i = 0; i < 8; i++) acc[i] = 0.f;

#pragma unroll 1
    for (int ci0 = 0; ci0 < 32; ci0 += 8) {
        __syncthreads();
        // stage input patch (zero-padded)
        for (int i = tid; i < 8 * 3 * 6 * 34; i += 512) {
            int ww = i % 34;
            int r2 = i / 34;
            int hh = r2 % 6; r2 /= 6;
            int tt = r2 % 3;
            int cil = r2 / 3;
            int gt = t + tt - 1, gh = h0 + hh - 1, gw = ww - 1;
            float v = 0.f;
            if (gt >= 0 && gt < T_ && gh >= 0 && gh < H_ && gw >= 0 && gw < W_)
                v = g_g[b * (C_ * THW_) + (ci0 + cil) * THW_ + gt * 1024 + gh * 32 + gw];
            ps[i] = v;
        }
        // stage weights co-contiguous
        for (int i = tid; i < 8 * 27 * 32; i += 512) {
            int co = i & 31;
            int r2 = i >> 5;
            int kk = r2 % 27;
            int cil = r2 / 27;
            ws[i] = cw[(co * 32 + ci0 + cil) * 27 + kk];
        }
        __syncthreads();

#pragma unroll 1
        for (int cil = 0; cil < 8; cil++) {
#pragma unroll 1
            for (int kt = 0; kt < 3; kt++) {
#pragma unroll
                for (int kh = 0; kh < 3; kh++) {
#pragma unroll
                    for (int kw = 0; kw < 3; kw++) {
                        float pv = ps[((cil * 3 + kt) * 6 + hl + kh) * 34 + w + kw];
                        const float4* wv = reinterpret_cast<const float4*>(
                            &ws[(cil * 27 + (kt * 9 + kh * 3 + kw)) * 32 + cog * 8]);
                        float4 w0 = wv[0];
                        float4 w1 = wv[1];
                        acc[0] = fmaf(pv, w0.x, acc[0]);
                        acc[1] = fmaf(pv, w0.y, acc[1]);
                        acc[2] = fmaf(pv, w0.z, acc[2]);
                        acc[3] = fmaf(pv, w0.w, acc[3]);
                        acc[4] = fmaf(pv, w1.x, acc[4]);
                        acc[5] = fmaf(pv, w1.y, acc[5]);
                        acc[6] = fmaf(pv, w1.z, acc[6]);
                        acc[7] = fmaf(pv, w1.w, acc[7]);
                    }
                }
            }
        }
    }

    const int h = h0 + hl;
    float sq = 0.f;
    const int base = b * (C_ * THW_) + t * 1024 + h * 32 + w;
#pragma unroll
    for (int i = 0; i < 8; i++) {
        int co = cog * 8 + i;
        int o = base + co * THW_;
        float gv = g_g[o];
        float val = 0.5f * gv + 0.5f * (acc[i] + bias_s[co]);
        out[o] = val;
        float d = val - f[o];
        sq = fmaf(d, d, sq);
    }
#pragma unroll
    for (int off = 16; off > 0; off >>= 1)
        sq += __shfl_down_sync(0xffffffffu, sq, off);
    if ((tid & 31) == 0) red[tid >> 5] = sq;
    __syncthreads();
    if (tid == 0) {
        float s = 0.f;
#pragma unroll
        for (int i = 0; i < 16; i++) s += red[i];
        atomicAdd(&g_loss, s);
    }
}

// ---------------- usage count ----------------
__global__ void usage_kernel() {
    int v = blockIdx.x * blockDim.x + threadIdx.x;
    bool u = (v < V_) && (g_counts[v] > 0);
    unsigned m = __ballot_sync(0xffffffffu, u);
    if ((threadIdx.x & 31) == 0) atomicAdd(&g_used, __popc(m));
}

// ---------------- finalize scalars ----------------
__global__ void finalize_kernel(float* __restrict__ out, int write_scalars) {
    if (!write_scalars) return;
    out[NELEM_]     = 1.25f * g_loss * (1.0f / (float)NELEM_);
    out[NELEM_ + 1] = 100.0f * (float)g_used / (float)V_;
}

extern "C" void kernel_launch(void* const* d_in, const int* in_sizes, int n_in,
                              void* d_out, int out_size) {
    const float* f    = (const float*)d_in[0];
    const float* emb  = (const float*)d_in[1];
    const float* cw   = (const float*)d_in[2];
    const float* cb   = (const float*)d_in[3];
    float* out = (float*)d_out;
    int write_scalars = (out_size >= NELEM_ + 2) ? 1 : 0;

    pack_kernel<<<NPAIR_ / 256, 256>>>(emb);
    argmin_kernel<<<N_ / 64, 256>>>(f);
    gather_kernel<<<NELEM_ / 256, 256>>>(emb);
    conv_kernel<<<B_ * T_ * (H_ / 4), 512>>>(f, cw, cb, out);
    usage_kernel<<<V_ / 256, 256>>>();
    finalize_kernel<<<1, 1>>>(out, write_scalars);
}